// round 7
// baseline (speedup 1.0000x reference)
#include <cuda_runtime.h>
#include <cstdint>
#include <math.h>

#define HH 128
#define WW 128
#define HWSZ (HH*WW)
#define BB 4
#define CINC 128
#define COUTC 128

typedef unsigned long long ull;

// ---------- packed f32x2 helpers (sm_100+ PTX) ----------
__device__ __forceinline__ ull ffma2(ull a, ull b, ull c) {
    ull d;
    asm("fma.rn.f32x2 %0, %1, %2, %3;" : "=l"(d) : "l"(a), "l"(b), "l"(c));
    return d;
}
__device__ __forceinline__ ull pack2(float x, float y) {
    ull r;
    unsigned xi = __float_as_uint(x), yi = __float_as_uint(y);
    asm("mov.b64 %0, {%1, %2};" : "=l"(r) : "r"(xi), "r"(yi));
    return r;
}
__device__ __forceinline__ void unpack2(ull v, float& x, float& y) {
    unsigned xi, yi;
    asm("mov.b64 {%0, %1}, %2;" : "=r"(xi), "=r"(yi) : "l"(v));
    x = __uint_as_float(xi);
    y = __uint_as_float(yi);
}

// ---------- scratch (no allocations allowed -> __device__ globals) ----------
__device__ float g_f1[BB * COUTC * HWSZ];        // 32 MB
__device__ float g_f2[BB * COUTC * HWSZ];        // 32 MB
__device__ float g_head[BB * 32 * HWSZ];         // 8 MB (27 used, padded to 32)
__device__ float g_w1T[261 * 9 * 128];
__device__ float g_w2T[128 * 9 * 128];
__device__ float g_w3T[128 * 9 * 128];
__device__ float g_w4T[128 * 9 * 32];
__device__ float g_wdT[128 * 9 * 128];
__device__ float g_b4p[32];

// ---------- prep: transpose OIHW weights to [cin][k][cout_pad] ----------
__global__ void transpose_w_kernel(const float* __restrict__ w, float* __restrict__ wT,
                                   int Cout, int Cin, int CoutPad) {
    int i = blockIdx.x * blockDim.x + threadIdx.x;
    int total = Cin * 9 * CoutPad;
    if (i >= total) return;
    int co = i % CoutPad;
    int t = i / CoutPad;
    int k = t % 9;
    int ci = t / 9;
    wT[i] = (co < Cout) ? w[(co * Cin + ci) * 9 + k] : 0.f;
}

__global__ void pad_bias_kernel(const float* __restrict__ b, float* __restrict__ bp,
                                int n, int np) {
    int i = threadIdx.x;
    if (i < np) bp[i] = (i < n) ? b[i] : 0.f;
}

// ---------- conv3x3 (SAME, stride 1), f32x2 register tile ----------
// block tile: 8 rows x 32 cols x 32 couts; thread: 4 px (W) x 8 couts.
template <bool LRELU>
__global__ __launch_bounds__(256, 2)
void conv3x3_kernel(const float* __restrict__ in, const float* __restrict__ wT,
                    const float* __restrict__ bias, float* __restrict__ out,
                    int Cin, int CoutTot) {
    __shared__ __align__(16) float xs[8][10][35];   // rows y0-1..y0+8, cols x0-1..x0+32 (34 used)
    __shared__ __align__(16) float ws[8][9][32];    // [cin_local][k][cout_local]

    const int tid = threadIdx.x;
    const int tx4 = (tid & 7) * 4;
    const int ty  = (tid >> 3) & 7;
    const int cz  = tid >> 6;            // 0..3 -> couts cz*8 .. cz*8+7
    const int x0 = blockIdx.x * 32;
    const int y0 = blockIdx.y * 8;
    const int ncg = CoutTot >> 5;
    const int b  = blockIdx.z / ncg;
    const int cg = blockIdx.z - b * ncg;
    const int cbase = cg * 32;

    ull acc[4][4];
    #pragma unroll
    for (int p = 0; p < 4; ++p)
        #pragma unroll
        for (int px = 0; px < 4; ++px) acc[p][px] = 0ull;

    const int nch = (Cin + 7) >> 3;
    for (int ch = 0; ch < nch; ++ch) {
        const int c0 = ch * 8;
        // stage input tile (zeros outside image / channel range)
        for (int i = tid; i < 8 * 10 * 34; i += 256) {
            int c = i / 340;
            int rm = i - c * 340;
            int r = rm / 34;
            int col = rm - r * 34;
            int ci = c0 + c;
            int gy = y0 - 1 + r;
            int gx = x0 - 1 + col;
            float v = 0.f;
            if (ci < Cin && (unsigned)gy < (unsigned)HH && (unsigned)gx < (unsigned)WW)
                v = in[((size_t)(b * Cin + ci) * HH + gy) * WW + gx];
            xs[c][r][col] = v;
        }
        // stage weights (coalesced from transposed layout)
        for (int i = tid; i < 8 * 9 * 32; i += 256) {
            int c = i / 288;
            int rm = i - c * 288;
            int k = rm >> 5;
            int co = rm & 31;
            int ci = c0 + c;
            ws[c][k][co] = (ci < Cin) ? wT[(size_t)(ci * 9 + k) * CoutTot + cbase + co] : 0.f;
        }
        __syncthreads();

        #pragma unroll 1
        for (int c = 0; c < 8; ++c) {
            ull pin[3][6];
            #pragma unroll
            for (int r = 0; r < 3; ++r)
                #pragma unroll
                for (int j = 0; j < 6; ++j) {
                    float v = xs[c][ty + r][tx4 + j];
                    pin[r][j] = pack2(v, v);
                }
            #pragma unroll
            for (int k = 0; k < 9; ++k) {
                const int r = k / 3, s = k - 3 * (k / 3);
                const ull* wp = (const ull*)&ws[c][k][cz * 8];
                ull w0 = wp[0], w1 = wp[1], w2 = wp[2], w3 = wp[3];
                #pragma unroll
                for (int px = 0; px < 4; ++px) {
                    ull v = pin[r][s + px];
                    acc[0][px] = ffma2(v, w0, acc[0][px]);
                    acc[1][px] = ffma2(v, w1, acc[1][px]);
                    acc[2][px] = ffma2(v, w2, acc[2][px]);
                    acc[3][px] = ffma2(v, w3, acc[3][px]);
                }
            }
        }
        __syncthreads();
    }

    // epilogue: bias (+optional leaky relu), vectorized stores
    const int y = y0 + ty;
    #pragma unroll
    for (int p = 0; p < 4; ++p) {
        int co = cbase + cz * 8 + 2 * p;
        float blo = bias[co], bhi = bias[co + 1];
        float4 vlo, vhi;
        float a, bb2;
        unpack2(acc[p][0], a, bb2); vlo.x = a + blo; vhi.x = bb2 + bhi;
        unpack2(acc[p][1], a, bb2); vlo.y = a + blo; vhi.y = bb2 + bhi;
        unpack2(acc[p][2], a, bb2); vlo.z = a + blo; vhi.z = bb2 + bhi;
        unpack2(acc[p][3], a, bb2); vlo.w = a + blo; vhi.w = bb2 + bhi;
        if (LRELU) {
            vlo.x = vlo.x >= 0.f ? vlo.x : 0.1f * vlo.x;
            vlo.y = vlo.y >= 0.f ? vlo.y : 0.1f * vlo.y;
            vlo.z = vlo.z >= 0.f ? vlo.z : 0.1f * vlo.z;
            vlo.w = vlo.w >= 0.f ? vlo.w : 0.1f * vlo.w;
            vhi.x = vhi.x >= 0.f ? vhi.x : 0.1f * vhi.x;
            vhi.y = vhi.y >= 0.f ? vhi.y : 0.1f * vhi.y;
            vhi.z = vhi.z >= 0.f ? vhi.z : 0.1f * vhi.z;
            vhi.w = vhi.w >= 0.f ? vhi.w : 0.1f * vhi.w;
        }
        float* o0 = out + ((size_t)(b * CoutTot + co) * HH + y) * WW + x0 + tx4;
        *(float4*)o0 = vlo;
        *(float4*)(o0 + HWSZ) = vhi;
    }
}

// ---------- modulated deformable conv ----------
// block tile: 16 (W) x 4 (H) pixels x all 128 couts; thread: 2 px x 16 couts.
__global__ __launch_bounds__(256, 2)
void deform_kernel(const float* __restrict__ x, const float* __restrict__ head,
                   const float* __restrict__ flow, const float* __restrict__ wdT,
                   const float* __restrict__ bias, float* __restrict__ out) {
    __shared__ __align__(16) float4 sw[576];      // [k*64+p] bilinear weights (mask folded)
    __shared__ __align__(16) int4  sidx[576];     // [k*64+p] clamped corner offsets
    __shared__ __align__(16) float wsm[4 * 9 * 128];  // [c][k][co]
    __shared__ __align__(16) float ssm[4 * 9 * 64];   // [c][k][p]

    const int tid = threadIdx.x;
    const int b = blockIdx.z;
    const int x0 = blockIdx.x * 16;
    const int y0 = blockIdx.y * 4;

    // phase 0: per-(tap, pixel) sampling parameters
    for (int e = tid; e < 576; e += 256) {
        int k = e >> 6;
        int p = e & 63;
        int y = y0 + (p >> 4);
        int xx = x0 + (p & 15);
        int pix = y * WW + xx;
        const float* hb = head + (size_t)b * 32 * HWSZ + pix;
        float dyr = hb[(2 * k) * HWSZ];
        float dxr = hb[(2 * k + 1) * HWSZ];
        float mr  = hb[(18 + k) * HWSZ];
        const float* fb = flow + (size_t)b * 2 * HWSZ + pix;
        float fx = fb[0];
        float fy = fb[HWSZ];
        // base = p - 1 + tap; offset = 3*tanh(head) + flipped flow
        float py = (float)(y - 1 + k / 3) + 3.0f * tanhf(dyr) + fy;
        float px = (float)(xx - 1 + (k - 3 * (k / 3))) + 3.0f * tanhf(dxr) + fx;
        float m = 1.0f / (1.0f + __expf(-mr));  // sigmoid(mask)
        float fy0 = floorf(py), fx0 = floorf(px);
        float ay = py - fy0, ax = px - fx0;
        int iy0 = (int)fy0, ix0 = (int)fx0;
        int iy1 = iy0 + 1, ix1 = ix0 + 1;
        float vy0 = (iy0 >= 0 && iy0 < HH) ? m : 0.f;
        float vy1 = (iy1 >= 0 && iy1 < HH) ? m : 0.f;
        float vx0 = (ix0 >= 0 && ix0 < WW) ? 1.f : 0.f;
        float vx1 = (ix1 >= 0 && ix1 < WW) ? 1.f : 0.f;
        float w00 = (1.f - ay) * (1.f - ax) * vy0 * vx0;
        float w01 = (1.f - ay) * ax * vy0 * vx1;
        float w10 = ay * (1.f - ax) * vy1 * vx0;
        float w11 = ay * ax * vy1 * vx1;
        int cy0 = min(max(iy0, 0), HH - 1), cy1 = min(max(iy1, 0), HH - 1);
        int cx0 = min(max(ix0, 0), WW - 1), cx1 = min(max(ix1, 0), WW - 1);
        sw[e] = make_float4(w00, w01, w10, w11);
        sidx[e] = make_int4(cy0 * WW + cx0, cy0 * WW + cx1, cy1 * WW + cx0, cy1 * WW + cx1);
    }

    const int g = tid >> 5;    // 0..7 -> couts g*16..g*16+15
    const int ph = tid & 31;   // pixel pair (2*ph, 2*ph+1)

    ull acc[2][8];
    #pragma unroll
    for (int q = 0; q < 8; ++q) {
        float b0 = bias[g * 16 + 2 * q];
        float b1 = bias[g * 16 + 2 * q + 1];
        acc[0][q] = pack2(b0, b1);
        acc[1][q] = pack2(b0, b1);
    }

    for (int c0 = 0; c0 < CINC; c0 += 4) {
        __syncthreads();  // prev GEMM done reading smem (and phase-0 visible on 1st iter)
        // stage chunk weights (contiguous in wdT)
        const float4* wsrc = (const float4*)(wdT + (size_t)c0 * 9 * 128);
        for (int i = tid; i < (4 * 9 * 128) / 4; i += 256)
            ((float4*)wsm)[i] = wsrc[i];
        // bilinear sampling for 4 channels x 9 taps x 64 px
        for (int e2 = tid; e2 < 4 * 576; e2 += 256) {
            int c = e2 / 576;
            int e = e2 - c * 576;
            float4 wv = sw[e];
            int4 iv = sidx[e];
            const float* xp = x + (size_t)(b * CINC + c0 + c) * HWSZ;
            float v = wv.x * __ldg(xp + iv.x) + wv.y * __ldg(xp + iv.y)
                    + wv.z * __ldg(xp + iv.z) + wv.w * __ldg(xp + iv.w);
            ssm[c * 576 + e] = v;
        }
        __syncthreads();

        // register GEMM: 36 (c,k) steps x 16 couts x 2 px
        #pragma unroll 4
        for (int ck = 0; ck < 36; ++ck) {
            float2 sv = *(const float2*)&ssm[ck * 64 + 2 * ph];
            ull s0 = pack2(sv.x, sv.x);
            ull s1 = pack2(sv.y, sv.y);
            const float4* wrow = (const float4*)&wsm[ck * 128 + g * 16];
            #pragma unroll
            for (int q4 = 0; q4 < 4; ++q4) {
                float4 wv = wrow[q4];
                ull w01 = pack2(wv.x, wv.y);
                ull w23 = pack2(wv.z, wv.w);
                acc[0][2 * q4]     = ffma2(s0, w01, acc[0][2 * q4]);
                acc[0][2 * q4 + 1] = ffma2(s0, w23, acc[0][2 * q4 + 1]);
                acc[1][2 * q4]     = ffma2(s1, w01, acc[1][2 * q4]);
                acc[1][2 * q4 + 1] = ffma2(s1, w23, acc[1][2 * q4 + 1]);
            }
        }
    }

    // epilogue: 16 couts x 2 adjacent px per thread
    int p0 = 2 * ph;
    int yy = y0 + (p0 >> 4);
    int xx = x0 + (p0 & 15);
    #pragma unroll
    for (int q = 0; q < 8; ++q) {
        int co = g * 16 + 2 * q;
        float a0, a1, c0v, c1v;
        unpack2(acc[0][q], a0, a1);
        unpack2(acc[1][q], c0v, c1v);
        float* o = out + ((size_t)(b * COUTC + co) * HH + yy) * WW + xx;
        *(float2*)o = make_float2(a0, c0v);
        *(float2*)(o + HWSZ) = make_float2(a1, c1v);
    }
}

// ---------- launcher ----------
extern "C" void kernel_launch(void* const* d_in, const int* in_sizes, int n_in,
                              void* d_out, int out_size) {
    const float* x    = (const float*)d_in[0];
    const float* cond = (const float*)d_in[1];
    const float* flow = (const float*)d_in[2];
    const float* w1 = (const float*)d_in[3];
    const float* b1 = (const float*)d_in[4];
    const float* w2 = (const float*)d_in[5];
    const float* b2 = (const float*)d_in[6];
    const float* w3 = (const float*)d_in[7];
    const float* b3 = (const float*)d_in[8];
    const float* w4 = (const float*)d_in[9];
    const float* b4 = (const float*)d_in[10];
    const float* wd = (const float*)d_in[11];
    const float* bd = (const float*)d_in[12];
    float* out = (float*)d_out;

    float *f1, *f2, *headp, *w1T, *w2T, *w3T, *w4T, *wdT, *b4p;
    cudaGetSymbolAddress((void**)&f1,   g_f1);
    cudaGetSymbolAddress((void**)&f2,   g_f2);
    cudaGetSymbolAddress((void**)&headp, g_head);
    cudaGetSymbolAddress((void**)&w1T,  g_w1T);
    cudaGetSymbolAddress((void**)&w2T,  g_w2T);
    cudaGetSymbolAddress((void**)&w3T,  g_w3T);
    cudaGetSymbolAddress((void**)&w4T,  g_w4T);
    cudaGetSymbolAddress((void**)&wdT,  g_wdT);
    cudaGetSymbolAddress((void**)&b4p,  g_b4p);

    const int CCOND = 261;

    transpose_w_kernel<<<(CCOND * 9 * 128 + 255) / 256, 256>>>(w1, w1T, 128, CCOND, 128);
    transpose_w_kernel<<<(128 * 9 * 128 + 255) / 256, 256>>>(w2, w2T, 128, 128, 128);
    transpose_w_kernel<<<(128 * 9 * 128 + 255) / 256, 256>>>(w3, w3T, 128, 128, 128);
    transpose_w_kernel<<<(128 * 9 * 32 + 255) / 256, 256>>>(w4, w4T, 27, 128, 32);
    transpose_w_kernel<<<(128 * 9 * 128 + 255) / 256, 256>>>(wd, wdT, 128, 128, 128);
    pad_bias_kernel<<<1, 32>>>(b4, b4p, 27, 32);

    dim3 g128(4, 16, 4 * 4);   // Wtiles, Htiles, B * cout_groups
    conv3x3_kernel<true><<<g128, 256>>>(cond, w1T, b1, f1, CCOND, 128);
    conv3x3_kernel<true><<<g128, 256>>>(f1, w2T, b2, f2, 128, 128);
    conv3x3_kernel<true><<<g128, 256>>>(f2, w3T, b3, f1, 128, 128);

    dim3 ghead(4, 16, 4 * 1);
    conv3x3_kernel<false><<<ghead, 256>>>(f1, w4T, b4p, headp, 128, 32);

    dim3 gdef(8, 32, 4);       // Wtiles(16), Htiles(4), B
    deform_kernel<<<gdef, 256>>>(x, headp, flow, wdT, bd, out);
}

// round 8
// speedup vs baseline: 1.0033x; 1.0033x over previous
#include <cuda_runtime.h>
#include <cstdint>
#include <math.h>

#define HH 128
#define WW 128
#define HWSZ (HH*WW)
#define BB 4
#define CINC 128
#define COUTC 128

typedef unsigned long long ull;

// ---------- packed f32x2 helpers (sm_100+ PTX) ----------
__device__ __forceinline__ ull ffma2(ull a, ull b, ull c) {
    ull d;
    asm("fma.rn.f32x2 %0, %1, %2, %3;" : "=l"(d) : "l"(a), "l"(b), "l"(c));
    return d;
}
__device__ __forceinline__ ull pack2(float x, float y) {
    ull r;
    unsigned xi = __float_as_uint(x), yi = __float_as_uint(y);
    asm("mov.b64 %0, {%1, %2};" : "=l"(r) : "r"(xi), "r"(yi));
    return r;
}
__device__ __forceinline__ void unpack2(ull v, float& x, float& y) {
    unsigned xi, yi;
    asm("mov.b64 {%0, %1}, %2;" : "=r"(xi), "=r"(yi) : "l"(v));
    x = __uint_as_float(xi);
    y = __uint_as_float(yi);
}

// ---------- scratch (no allocations allowed -> __device__ globals) ----------
__device__ float g_f1[BB * COUTC * HWSZ];        // 32 MB
__device__ float g_f2[BB * COUTC * HWSZ];        // 32 MB
__device__ float g_head[BB * 32 * HWSZ];         // 8 MB (27 used, padded to 32)
__device__ float g_w1T[261 * 9 * 128];
__device__ float g_w2T[128 * 9 * 128];
__device__ float g_w3T[128 * 9 * 128];
__device__ float g_w4T[128 * 9 * 32];
__device__ float g_wdT[128 * 9 * 128];
__device__ float g_b4p[32];

// ---------- prep: transpose OIHW weights to [cin][k][cout_pad] ----------
__global__ void transpose_w_kernel(const float* __restrict__ w, float* __restrict__ wT,
                                   int Cout, int Cin, int CoutPad) {
    int i = blockIdx.x * blockDim.x + threadIdx.x;
    int total = Cin * 9 * CoutPad;
    if (i >= total) return;
    int co = i % CoutPad;
    int t = i / CoutPad;
    int k = t % 9;
    int ci = t / 9;
    wT[i] = (co < Cout) ? w[(co * Cin + ci) * 9 + k] : 0.f;
}

__global__ void pad_bias_kernel(const float* __restrict__ b, float* __restrict__ bp,
                                int n, int np) {
    int i = threadIdx.x;
    if (i < np) bp[i] = (i < n) ? b[i] : 0.f;
}

// ---------- conv3x3 (SAME, stride 1), f32x2 register tile ----------
// block tile: 8 rows x 32 cols x 32 couts; thread: 4 px (W) x 8 couts.
template <bool LRELU>
__global__ __launch_bounds__(256, 2)
void conv3x3_kernel(const float* __restrict__ in, const float* __restrict__ wT,
                    const float* __restrict__ bias, float* __restrict__ out,
                    int Cin, int CoutTot) {
    __shared__ __align__(16) float xs[8][10][35];   // rows y0-1..y0+8, cols x0-1..x0+32 (34 used)
    __shared__ __align__(16) float ws[8][9][32];    // [cin_local][k][cout_local]

    const int tid = threadIdx.x;
    const int tx4 = (tid & 7) * 4;
    const int ty  = (tid >> 3) & 7;
    const int cz  = tid >> 6;            // 0..3 -> couts cz*8 .. cz*8+7
    const int x0 = blockIdx.x * 32;
    const int y0 = blockIdx.y * 8;
    const int ncg = CoutTot >> 5;
    const int b  = blockIdx.z / ncg;
    const int cg = blockIdx.z - b * ncg;
    const int cbase = cg * 32;

    ull acc[4][4];
    #pragma unroll
    for (int p = 0; p < 4; ++p)
        #pragma unroll
        for (int px = 0; px < 4; ++px) acc[p][px] = 0ull;

    const int nch = (Cin + 7) >> 3;
    for (int ch = 0; ch < nch; ++ch) {
        const int c0 = ch * 8;
        // stage input tile (zeros outside image / channel range)
        for (int i = tid; i < 8 * 10 * 34; i += 256) {
            int c = i / 340;
            int rm = i - c * 340;
            int r = rm / 34;
            int col = rm - r * 34;
            int ci = c0 + c;
            int gy = y0 - 1 + r;
            int gx = x0 - 1 + col;
            float v = 0.f;
            if (ci < Cin && (unsigned)gy < (unsigned)HH && (unsigned)gx < (unsigned)WW)
                v = in[((size_t)(b * Cin + ci) * HH + gy) * WW + gx];
            xs[c][r][col] = v;
        }
        // stage weights (coalesced from transposed layout)
        for (int i = tid; i < 8 * 9 * 32; i += 256) {
            int c = i / 288;
            int rm = i - c * 288;
            int k = rm >> 5;
            int co = rm & 31;
            int ci = c0 + c;
            ws[c][k][co] = (ci < Cin) ? wT[(size_t)(ci * 9 + k) * CoutTot + cbase + co] : 0.f;
        }
        __syncthreads();

        #pragma unroll 1
        for (int c = 0; c < 8; ++c) {
            ull pin[3][6];
            #pragma unroll
            for (int r = 0; r < 3; ++r)
                #pragma unroll
                for (int j = 0; j < 6; ++j) {
                    float v = xs[c][ty + r][tx4 + j];
                    pin[r][j] = pack2(v, v);
                }
            #pragma unroll
            for (int k = 0; k < 9; ++k) {
                const int r = k / 3, s = k - 3 * (k / 3);
                const ull* wp = (const ull*)&ws[c][k][cz * 8];
                ull w0 = wp[0], w1 = wp[1], w2 = wp[2], w3 = wp[3];
                #pragma unroll
                for (int px = 0; px < 4; ++px) {
                    ull v = pin[r][s + px];
                    acc[0][px] = ffma2(v, w0, acc[0][px]);
                    acc[1][px] = ffma2(v, w1, acc[1][px]);
                    acc[2][px] = ffma2(v, w2, acc[2][px]);
                    acc[3][px] = ffma2(v, w3, acc[3][px]);
                }
            }
        }
        __syncthreads();
    }

    // epilogue: bias (+optional leaky relu), vectorized stores
    const int y = y0 + ty;
    #pragma unroll
    for (int p = 0; p < 4; ++p) {
        int co = cbase + cz * 8 + 2 * p;
        float blo = bias[co], bhi = bias[co + 1];
        float4 vlo, vhi;
        float a, bb2;
        unpack2(acc[p][0], a, bb2); vlo.x = a + blo; vhi.x = bb2 + bhi;
        unpack2(acc[p][1], a, bb2); vlo.y = a + blo; vhi.y = bb2 + bhi;
        unpack2(acc[p][2], a, bb2); vlo.z = a + blo; vhi.z = bb2 + bhi;
        unpack2(acc[p][3], a, bb2); vlo.w = a + blo; vhi.w = bb2 + bhi;
        if (LRELU) {
            vlo.x = vlo.x >= 0.f ? vlo.x : 0.1f * vlo.x;
            vlo.y = vlo.y >= 0.f ? vlo.y : 0.1f * vlo.y;
            vlo.z = vlo.z >= 0.f ? vlo.z : 0.1f * vlo.z;
            vlo.w = vlo.w >= 0.f ? vlo.w : 0.1f * vlo.w;
            vhi.x = vhi.x >= 0.f ? vhi.x : 0.1f * vhi.x;
            vhi.y = vhi.y >= 0.f ? vhi.y : 0.1f * vhi.y;
            vhi.z = vhi.z >= 0.f ? vhi.z : 0.1f * vhi.z;
            vhi.w = vhi.w >= 0.f ? vhi.w : 0.1f * vhi.w;
        }
        float* o0 = out + ((size_t)(b * CoutTot + co) * HH + y) * WW + x0 + tx4;
        *(float4*)o0 = vlo;
        *(float4*)(o0 + HWSZ) = vhi;
    }
}

// ---------- modulated deformable conv ----------
// block tile: 16 (W) x 4 (H) pixels x all 128 couts; thread: 2 px x 16 couts.
__global__ __launch_bounds__(256, 2)
void deform_kernel(const float* __restrict__ x, const float* __restrict__ head,
                   const float* __restrict__ flow, const float* __restrict__ wdT,
                   const float* __restrict__ bias, float* __restrict__ out) {
    __shared__ __align__(16) float4 sw[576];      // [k*64+p] bilinear weights (mask folded)
    __shared__ __align__(16) int4  sidx[576];     // [k*64+p] clamped corner offsets
    __shared__ __align__(16) float wsm[4 * 9 * 128];  // [c][k][co]
    __shared__ __align__(16) float ssm[4 * 9 * 64];   // [c][k][p]

    const int tid = threadIdx.x;
    const int b = blockIdx.z;
    const int x0 = blockIdx.x * 16;
    const int y0 = blockIdx.y * 4;

    // phase 0: per-(tap, pixel) sampling parameters
    for (int e = tid; e < 576; e += 256) {
        int k = e >> 6;
        int p = e & 63;
        int y = y0 + (p >> 4);
        int xx = x0 + (p & 15);
        int pix = y * WW + xx;
        const float* hb = head + (size_t)b * 32 * HWSZ + pix;
        float dyr = hb[(2 * k) * HWSZ];
        float dxr = hb[(2 * k + 1) * HWSZ];
        float mr  = hb[(18 + k) * HWSZ];
        const float* fb = flow + (size_t)b * 2 * HWSZ + pix;
        float fx = fb[0];
        float fy = fb[HWSZ];
        // base = p - 1 + tap; offset = 3*tanh(head) + flipped flow
        float py = (float)(y - 1 + k / 3) + 3.0f * tanhf(dyr) + fy;
        float px = (float)(xx - 1 + (k - 3 * (k / 3))) + 3.0f * tanhf(dxr) + fx;
        float m = 1.0f / (1.0f + __expf(-mr));  // sigmoid(mask)
        float fy0 = floorf(py), fx0 = floorf(px);
        float ay = py - fy0, ax = px - fx0;
        int iy0 = (int)fy0, ix0 = (int)fx0;
        int iy1 = iy0 + 1, ix1 = ix0 + 1;
        float vy0 = (iy0 >= 0 && iy0 < HH) ? m : 0.f;
        float vy1 = (iy1 >= 0 && iy1 < HH) ? m : 0.f;
        float vx0 = (ix0 >= 0 && ix0 < WW) ? 1.f : 0.f;
        float vx1 = (ix1 >= 0 && ix1 < WW) ? 1.f : 0.f;
        float w00 = (1.f - ay) * (1.f - ax) * vy0 * vx0;
        float w01 = (1.f - ay) * ax * vy0 * vx1;
        float w10 = ay * (1.f - ax) * vy1 * vx0;
        float w11 = ay * ax * vy1 * vx1;
        int cy0 = min(max(iy0, 0), HH - 1), cy1 = min(max(iy1, 0), HH - 1);
        int cx0 = min(max(ix0, 0), WW - 1), cx1 = min(max(ix1, 0), WW - 1);
        sw[e] = make_float4(w00, w01, w10, w11);
        sidx[e] = make_int4(cy0 * WW + cx0, cy0 * WW + cx1, cy1 * WW + cx0, cy1 * WW + cx1);
    }

    const int g = tid >> 5;    // 0..7 -> couts g*16..g*16+15
    const int ph = tid & 31;   // pixel pair (2*ph, 2*ph+1)

    ull acc[2][8];
    #pragma unroll
    for (int q = 0; q < 8; ++q) {
        float b0 = bias[g * 16 + 2 * q];
        float b1 = bias[g * 16 + 2 * q + 1];
        acc[0][q] = pack2(b0, b1);
        acc[1][q] = pack2(b0, b1);
    }

    for (int c0 = 0; c0 < CINC; c0 += 4) {
        __syncthreads();  // prev GEMM done reading smem (and phase-0 visible on 1st iter)
        // stage chunk weights (contiguous in wdT)
        const float4* wsrc = (const float4*)(wdT + (size_t)c0 * 9 * 128);
        for (int i = tid; i < (4 * 9 * 128) / 4; i += 256)
            ((float4*)wsm)[i] = wsrc[i];
        // bilinear sampling for 4 channels x 9 taps x 64 px
        for (int e2 = tid; e2 < 4 * 576; e2 += 256) {
            int c = e2 / 576;
            int e = e2 - c * 576;
            float4 wv = sw[e];
            int4 iv = sidx[e];
            const float* xp = x + (size_t)(b * CINC + c0 + c) * HWSZ;
            float v = wv.x * __ldg(xp + iv.x) + wv.y * __ldg(xp + iv.y)
                    + wv.z * __ldg(xp + iv.z) + wv.w * __ldg(xp + iv.w);
            ssm[c * 576 + e] = v;
        }
        __syncthreads();

        // register GEMM: 36 (c,k) steps x 16 couts x 2 px
        #pragma unroll 4
        for (int ck = 0; ck < 36; ++ck) {
            float2 sv = *(const float2*)&ssm[ck * 64 + 2 * ph];
            ull s0 = pack2(sv.x, sv.x);
            ull s1 = pack2(sv.y, sv.y);
            const float4* wrow = (const float4*)&wsm[ck * 128 + g * 16];
            #pragma unroll
            for (int q4 = 0; q4 < 4; ++q4) {
                float4 wv = wrow[q4];
                ull w01 = pack2(wv.x, wv.y);
                ull w23 = pack2(wv.z, wv.w);
                acc[0][2 * q4]     = ffma2(s0, w01, acc[0][2 * q4]);
                acc[0][2 * q4 + 1] = ffma2(s0, w23, acc[0][2 * q4 + 1]);
                acc[1][2 * q4]     = ffma2(s1, w01, acc[1][2 * q4]);
                acc[1][2 * q4 + 1] = ffma2(s1, w23, acc[1][2 * q4 + 1]);
            }
        }
    }

    // epilogue: 16 couts x 2 adjacent px per thread
    int p0 = 2 * ph;
    int yy = y0 + (p0 >> 4);
    int xx = x0 + (p0 & 15);
    #pragma unroll
    for (int q = 0; q < 8; ++q) {
        int co = g * 16 + 2 * q;
        float a0, a1, c0v, c1v;
        unpack2(acc[0][q], a0, a1);
        unpack2(acc[1][q], c0v, c1v);
        float* o = out + ((size_t)(b * COUTC + co) * HH + yy) * WW + xx;
        *(float2*)o = make_float2(a0, c0v);
        *(float2*)(o + HWSZ) = make_float2(a1, c1v);
    }
}

// ---------- launcher ----------
extern "C" void kernel_launch(void* const* d_in, const int* in_sizes, int n_in,
                              void* d_out, int out_size) {
    const float* x    = (const float*)d_in[0];
    const float* cond = (const float*)d_in[1];
    const float* flow = (const float*)d_in[2];
    const float* w1 = (const float*)d_in[3];
    const float* b1 = (const float*)d_in[4];
    const float* w2 = (const float*)d_in[5];
    const float* b2 = (const float*)d_in[6];
    const float* w3 = (const float*)d_in[7];
    const float* b3 = (const float*)d_in[8];
    const float* w4 = (const float*)d_in[9];
    const float* b4 = (const float*)d_in[10];
    const float* wd = (const float*)d_in[11];
    const float* bd = (const float*)d_in[12];
    float* out = (float*)d_out;

    float *f1, *f2, *headp, *w1T, *w2T, *w3T, *w4T, *wdT, *b4p;
    cudaGetSymbolAddress((void**)&f1,   g_f1);
    cudaGetSymbolAddress((void**)&f2,   g_f2);
    cudaGetSymbolAddress((void**)&headp, g_head);
    cudaGetSymbolAddress((void**)&w1T,  g_w1T);
    cudaGetSymbolAddress((void**)&w2T,  g_w2T);
    cudaGetSymbolAddress((void**)&w3T,  g_w3T);
    cudaGetSymbolAddress((void**)&w4T,  g_w4T);
    cudaGetSymbolAddress((void**)&wdT,  g_wdT);
    cudaGetSymbolAddress((void**)&b4p,  g_b4p);

    const int CCOND = 261;

    transpose_w_kernel<<<(CCOND * 9 * 128 + 255) / 256, 256>>>(w1, w1T, 128, CCOND, 128);
    transpose_w_kernel<<<(128 * 9 * 128 + 255) / 256, 256>>>(w2, w2T, 128, 128, 128);
    transpose_w_kernel<<<(128 * 9 * 128 + 255) / 256, 256>>>(w3, w3T, 128, 128, 128);
    transpose_w_kernel<<<(128 * 9 * 32 + 255) / 256, 256>>>(w4, w4T, 27, 128, 32);
    transpose_w_kernel<<<(128 * 9 * 128 + 255) / 256, 256>>>(wd, wdT, 128, 128, 128);
    pad_bias_kernel<<<1, 32>>>(b4, b4p, 27, 32);

    dim3 g128(4, 16, 4 * 4);   // Wtiles, Htiles, B * cout_groups
    conv3x3_kernel<true><<<g128, 256>>>(cond, w1T, b1, f1, CCOND, 128);
    conv3x3_kernel<true><<<g128, 256>>>(f1, w2T, b2, f2, 128, 128);
    conv3x3_kernel<true><<<g128, 256>>>(f2, w3T, b3, f1, 128, 128);

    dim3 ghead(4, 16, 4 * 1);
    conv3x3_kernel<false><<<ghead, 256>>>(f1, w4T, b4p, headp, 128, 32);

    dim3 gdef(8, 32, 4);       // Wtiles(16), Htiles(4), B
    deform_kernel<<<gdef, 256>>>(x, headp, flow, wdT, bd, out);
}

// round 9
// speedup vs baseline: 1.0043x; 1.0010x over previous
#include <cuda_runtime.h>
#include <cstdint>
#include <math.h>

#define HH 128
#define WW 128
#define HWSZ (HH*WW)
#define BB 4
#define CINC 128
#define COUTC 128

typedef unsigned long long ull;

// ---------- packed f32x2 helpers (sm_100+ PTX) ----------
__device__ __forceinline__ ull ffma2(ull a, ull b, ull c) {
    ull d;
    asm("fma.rn.f32x2 %0, %1, %2, %3;" : "=l"(d) : "l"(a), "l"(b), "l"(c));
    return d;
}
__device__ __forceinline__ ull pack2(float x, float y) {
    ull r;
    unsigned xi = __float_as_uint(x), yi = __float_as_uint(y);
    asm("mov.b64 %0, {%1, %2};" : "=l"(r) : "r"(xi), "r"(yi));
    return r;
}
__device__ __forceinline__ void unpack2(ull v, float& x, float& y) {
    unsigned xi, yi;
    asm("mov.b64 {%0, %1}, %2;" : "=r"(xi), "=r"(yi) : "l"(v));
    x = __uint_as_float(xi);
    y = __uint_as_float(yi);
}

// ---------- scratch (no allocations allowed -> __device__ globals) ----------
__device__ float g_f1[BB * COUTC * HWSZ];        // 32 MB
__device__ float g_f2[BB * COUTC * HWSZ];        // 32 MB
__device__ float g_head[BB * 32 * HWSZ];         // 8 MB (27 used, padded to 32)
__device__ float g_w1T[261 * 9 * 128];
__device__ float g_w2T[128 * 9 * 128];
__device__ float g_w3T[128 * 9 * 128];
__device__ float g_w4T[128 * 9 * 32];
__device__ float g_wdT[128 * 9 * 128];
__device__ float g_b4p[32];

// ---------- prep: transpose OIHW weights to [cin][k][cout_pad] ----------
__global__ void transpose_w_kernel(const float* __restrict__ w, float* __restrict__ wT,
                                   int Cout, int Cin, int CoutPad) {
    int i = blockIdx.x * blockDim.x + threadIdx.x;
    int total = Cin * 9 * CoutPad;
    if (i >= total) return;
    int co = i % CoutPad;
    int t = i / CoutPad;
    int k = t % 9;
    int ci = t / 9;
    wT[i] = (co < Cout) ? w[(co * Cin + ci) * 9 + k] : 0.f;
}

__global__ void pad_bias_kernel(const float* __restrict__ b, float* __restrict__ bp,
                                int n, int np) {
    int i = threadIdx.x;
    if (i < np) bp[i] = (i < n) ? b[i] : 0.f;
}

// ---------- conv3x3 (SAME, stride 1), f32x2 register tile ----------
// block tile: 8 rows x 32 cols x 32 couts; thread: 4 px (W) x 8 couts.
template <bool LRELU>
__global__ __launch_bounds__(256, 2)
void conv3x3_kernel(const float* __restrict__ in, const float* __restrict__ wT,
                    const float* __restrict__ bias, float* __restrict__ out,
                    int Cin, int CoutTot) {
    __shared__ __align__(16) float xs[8][10][35];   // rows y0-1..y0+8, cols x0-1..x0+32 (34 used)
    __shared__ __align__(16) float ws[8][9][32];    // [cin_local][k][cout_local]

    const int tid = threadIdx.x;
    const int tx4 = (tid & 7) * 4;
    const int ty  = (tid >> 3) & 7;
    const int cz  = tid >> 6;            // 0..3 -> couts cz*8 .. cz*8+7
    const int x0 = blockIdx.x * 32;
    const int y0 = blockIdx.y * 8;
    const int ncg = CoutTot >> 5;
    const int b  = blockIdx.z / ncg;
    const int cg = blockIdx.z - b * ncg;
    const int cbase = cg * 32;

    ull acc[4][4];
    #pragma unroll
    for (int p = 0; p < 4; ++p)
        #pragma unroll
        for (int px = 0; px < 4; ++px) acc[p][px] = 0ull;

    const int nch = (Cin + 7) >> 3;
    for (int ch = 0; ch < nch; ++ch) {
        const int c0 = ch * 8;
        // stage input tile (zeros outside image / channel range)
        for (int i = tid; i < 8 * 10 * 34; i += 256) {
            int c = i / 340;
            int rm = i - c * 340;
            int r = rm / 34;
            int col = rm - r * 34;
            int ci = c0 + c;
            int gy = y0 - 1 + r;
            int gx = x0 - 1 + col;
            float v = 0.f;
            if (ci < Cin && (unsigned)gy < (unsigned)HH && (unsigned)gx < (unsigned)WW)
                v = in[((size_t)(b * Cin + ci) * HH + gy) * WW + gx];
            xs[c][r][col] = v;
        }
        // stage weights (coalesced from transposed layout)
        for (int i = tid; i < 8 * 9 * 32; i += 256) {
            int c = i / 288;
            int rm = i - c * 288;
            int k = rm >> 5;
            int co = rm & 31;
            int ci = c0 + c;
            ws[c][k][co] = (ci < Cin) ? wT[(size_t)(ci * 9 + k) * CoutTot + cbase + co] : 0.f;
        }
        __syncthreads();

        #pragma unroll 1
        for (int c = 0; c < 8; ++c) {
            ull pin[3][6];
            #pragma unroll
            for (int r = 0; r < 3; ++r)
                #pragma unroll
                for (int j = 0; j < 6; ++j) {
                    float v = xs[c][ty + r][tx4 + j];
                    pin[r][j] = pack2(v, v);
                }
            #pragma unroll
            for (int k = 0; k < 9; ++k) {
                const int r = k / 3, s = k - 3 * (k / 3);
                const ull* wp = (const ull*)&ws[c][k][cz * 8];
                ull w0 = wp[0], w1 = wp[1], w2 = wp[2], w3 = wp[3];
                #pragma unroll
                for (int px = 0; px < 4; ++px) {
                    ull v = pin[r][s + px];
                    acc[0][px] = ffma2(v, w0, acc[0][px]);
                    acc[1][px] = ffma2(v, w1, acc[1][px]);
                    acc[2][px] = ffma2(v, w2, acc[2][px]);
                    acc[3][px] = ffma2(v, w3, acc[3][px]);
                }
            }
        }
        __syncthreads();
    }

    // epilogue: bias (+optional leaky relu), vectorized stores
    const int y = y0 + ty;
    #pragma unroll
    for (int p = 0; p < 4; ++p) {
        int co = cbase + cz * 8 + 2 * p;
        float blo = bias[co], bhi = bias[co + 1];
        float4 vlo, vhi;
        float a, bb2;
        unpack2(acc[p][0], a, bb2); vlo.x = a + blo; vhi.x = bb2 + bhi;
        unpack2(acc[p][1], a, bb2); vlo.y = a + blo; vhi.y = bb2 + bhi;
        unpack2(acc[p][2], a, bb2); vlo.z = a + blo; vhi.z = bb2 + bhi;
        unpack2(acc[p][3], a, bb2); vlo.w = a + blo; vhi.w = bb2 + bhi;
        if (LRELU) {
            vlo.x = vlo.x >= 0.f ? vlo.x : 0.1f * vlo.x;
            vlo.y = vlo.y >= 0.f ? vlo.y : 0.1f * vlo.y;
            vlo.z = vlo.z >= 0.f ? vlo.z : 0.1f * vlo.z;
            vlo.w = vlo.w >= 0.f ? vlo.w : 0.1f * vlo.w;
            vhi.x = vhi.x >= 0.f ? vhi.x : 0.1f * vhi.x;
            vhi.y = vhi.y >= 0.f ? vhi.y : 0.1f * vhi.y;
            vhi.z = vhi.z >= 0.f ? vhi.z : 0.1f * vhi.z;
            vhi.w = vhi.w >= 0.f ? vhi.w : 0.1f * vhi.w;
        }
        float* o0 = out + ((size_t)(b * CoutTot + co) * HH + y) * WW + x0 + tx4;
        *(float4*)o0 = vlo;
        *(float4*)(o0 + HWSZ) = vhi;
    }
}

// ---------- modulated deformable conv ----------
// block tile: 16 (W) x 4 (H) pixels x all 128 couts; thread: 2 px x 16 couts.
__global__ __launch_bounds__(256, 2)
void deform_kernel(const float* __restrict__ x, const float* __restrict__ head,
                   const float* __restrict__ flow, const float* __restrict__ wdT,
                   const float* __restrict__ bias, float* __restrict__ out) {
    __shared__ __align__(16) float4 sw[576];      // [k*64+p] bilinear weights (mask folded)
    __shared__ __align__(16) int4  sidx[576];     // [k*64+p] clamped corner offsets
    __shared__ __align__(16) float wsm[4 * 9 * 128];  // [c][k][co]
    __shared__ __align__(16) float ssm[4 * 9 * 64];   // [c][k][p]

    const int tid = threadIdx.x;
    const int b = blockIdx.z;
    const int x0 = blockIdx.x * 16;
    const int y0 = blockIdx.y * 4;

    // phase 0: per-(tap, pixel) sampling parameters
    for (int e = tid; e < 576; e += 256) {
        int k = e >> 6;
        int p = e & 63;
        int y = y0 + (p >> 4);
        int xx = x0 + (p & 15);
        int pix = y * WW + xx;
        const float* hb = head + (size_t)b * 32 * HWSZ + pix;
        float dyr = hb[(2 * k) * HWSZ];
        float dxr = hb[(2 * k + 1) * HWSZ];
        float mr  = hb[(18 + k) * HWSZ];
        const float* fb = flow + (size_t)b * 2 * HWSZ + pix;
        float fx = fb[0];
        float fy = fb[HWSZ];
        // base = p - 1 + tap; offset = 3*tanh(head) + flipped flow
        float py = (float)(y - 1 + k / 3) + 3.0f * tanhf(dyr) + fy;
        float px = (float)(xx - 1 + (k - 3 * (k / 3))) + 3.0f * tanhf(dxr) + fx;
        float m = 1.0f / (1.0f + __expf(-mr));  // sigmoid(mask)
        float fy0 = floorf(py), fx0 = floorf(px);
        float ay = py - fy0, ax = px - fx0;
        int iy0 = (int)fy0, ix0 = (int)fx0;
        int iy1 = iy0 + 1, ix1 = ix0 + 1;
        float vy0 = (iy0 >= 0 && iy0 < HH) ? m : 0.f;
        float vy1 = (iy1 >= 0 && iy1 < HH) ? m : 0.f;
        float vx0 = (ix0 >= 0 && ix0 < WW) ? 1.f : 0.f;
        float vx1 = (ix1 >= 0 && ix1 < WW) ? 1.f : 0.f;
        float w00 = (1.f - ay) * (1.f - ax) * vy0 * vx0;
        float w01 = (1.f - ay) * ax * vy0 * vx1;
        float w10 = ay * (1.f - ax) * vy1 * vx0;
        float w11 = ay * ax * vy1 * vx1;
        int cy0 = min(max(iy0, 0), HH - 1), cy1 = min(max(iy1, 0), HH - 1);
        int cx0 = min(max(ix0, 0), WW - 1), cx1 = min(max(ix1, 0), WW - 1);
        sw[e] = make_float4(w00, w01, w10, w11);
        sidx[e] = make_int4(cy0 * WW + cx0, cy0 * WW + cx1, cy1 * WW + cx0, cy1 * WW + cx1);
    }

    const int g = tid >> 5;    // 0..7 -> couts g*16..g*16+15
    const int ph = tid & 31;   // pixel pair (2*ph, 2*ph+1)

    ull acc[2][8];
    #pragma unroll
    for (int q = 0; q < 8; ++q) {
        float b0 = bias[g * 16 + 2 * q];
        float b1 = bias[g * 16 + 2 * q + 1];
        acc[0][q] = pack2(b0, b1);
        acc[1][q] = pack2(b0, b1);
    }

    for (int c0 = 0; c0 < CINC; c0 += 4) {
        __syncthreads();  // prev GEMM done reading smem (and phase-0 visible on 1st iter)
        // stage chunk weights (contiguous in wdT)
        const float4* wsrc = (const float4*)(wdT + (size_t)c0 * 9 * 128);
        for (int i = tid; i < (4 * 9 * 128) / 4; i += 256)
            ((float4*)wsm)[i] = wsrc[i];
        // bilinear sampling for 4 channels x 9 taps x 64 px
        for (int e2 = tid; e2 < 4 * 576; e2 += 256) {
            int c = e2 / 576;
            int e = e2 - c * 576;
            float4 wv = sw[e];
            int4 iv = sidx[e];
            const float* xp = x + (size_t)(b * CINC + c0 + c) * HWSZ;
            float v = wv.x * __ldg(xp + iv.x) + wv.y * __ldg(xp + iv.y)
                    + wv.z * __ldg(xp + iv.z) + wv.w * __ldg(xp + iv.w);
            ssm[c * 576 + e] = v;
        }
        __syncthreads();

        // register GEMM: 36 (c,k) steps x 16 couts x 2 px
        #pragma unroll 4
        for (int ck = 0; ck < 36; ++ck) {
            float2 sv = *(const float2*)&ssm[ck * 64 + 2 * ph];
            ull s0 = pack2(sv.x, sv.x);
            ull s1 = pack2(sv.y, sv.y);
            const float4* wrow = (const float4*)&wsm[ck * 128 + g * 16];
            #pragma unroll
            for (int q4 = 0; q4 < 4; ++q4) {
                float4 wv = wrow[q4];
                ull w01 = pack2(wv.x, wv.y);
                ull w23 = pack2(wv.z, wv.w);
                acc[0][2 * q4]     = ffma2(s0, w01, acc[0][2 * q4]);
                acc[0][2 * q4 + 1] = ffma2(s0, w23, acc[0][2 * q4 + 1]);
                acc[1][2 * q4]     = ffma2(s1, w01, acc[1][2 * q4]);
                acc[1][2 * q4 + 1] = ffma2(s1, w23, acc[1][2 * q4 + 1]);
            }
        }
    }

    // epilogue: 16 couts x 2 adjacent px per thread
    int p0 = 2 * ph;
    int yy = y0 + (p0 >> 4);
    int xx = x0 + (p0 & 15);
    #pragma unroll
    for (int q = 0; q < 8; ++q) {
        int co = g * 16 + 2 * q;
        float a0, a1, c0v, c1v;
        unpack2(acc[0][q], a0, a1);
        unpack2(acc[1][q], c0v, c1v);
        float* o = out + ((size_t)(b * COUTC + co) * HH + yy) * WW + xx;
        *(float2*)o = make_float2(a0, c0v);
        *(float2*)(o + HWSZ) = make_float2(a1, c1v);
    }
}

// ---------- launcher ----------
extern "C" void kernel_launch(void* const* d_in, const int* in_sizes, int n_in,
                              void* d_out, int out_size) {
    const float* x    = (const float*)d_in[0];
    const float* cond = (const float*)d_in[1];
    const float* flow = (const float*)d_in[2];
    const float* w1 = (const float*)d_in[3];
    const float* b1 = (const float*)d_in[4];
    const float* w2 = (const float*)d_in[5];
    const float* b2 = (const float*)d_in[6];
    const float* w3 = (const float*)d_in[7];
    const float* b3 = (const float*)d_in[8];
    const float* w4 = (const float*)d_in[9];
    const float* b4 = (const float*)d_in[10];
    const float* wd = (const float*)d_in[11];
    const float* bd = (const float*)d_in[12];
    float* out = (float*)d_out;

    float *f1, *f2, *headp, *w1T, *w2T, *w3T, *w4T, *wdT, *b4p;
    cudaGetSymbolAddress((void**)&f1,   g_f1);
    cudaGetSymbolAddress((void**)&f2,   g_f2);
    cudaGetSymbolAddress((void**)&headp, g_head);
    cudaGetSymbolAddress((void**)&w1T,  g_w1T);
    cudaGetSymbolAddress((void**)&w2T,  g_w2T);
    cudaGetSymbolAddress((void**)&w3T,  g_w3T);
    cudaGetSymbolAddress((void**)&w4T,  g_w4T);
    cudaGetSymbolAddress((void**)&wdT,  g_wdT);
    cudaGetSymbolAddress((void**)&b4p,  g_b4p);

    const int CCOND = 261;

    transpose_w_kernel<<<(CCOND * 9 * 128 + 255) / 256, 256>>>(w1, w1T, 128, CCOND, 128);
    transpose_w_kernel<<<(128 * 9 * 128 + 255) / 256, 256>>>(w2, w2T, 128, 128, 128);
    transpose_w_kernel<<<(128 * 9 * 128 + 255) / 256, 256>>>(w3, w3T, 128, 128, 128);
    transpose_w_kernel<<<(128 * 9 * 32 + 255) / 256, 256>>>(w4, w4T, 27, 128, 32);
    transpose_w_kernel<<<(128 * 9 * 128 + 255) / 256, 256>>>(wd, wdT, 128, 128, 128);
    pad_bias_kernel<<<1, 32>>>(b4, b4p, 27, 32);

    dim3 g128(4, 16, 4 * 4);   // Wtiles, Htiles, B * cout_groups
    conv3x3_kernel<true><<<g128, 256>>>(cond, w1T, b1, f1, CCOND, 128);
    conv3x3_kernel<true><<<g128, 256>>>(f1, w2T, b2, f2, 128, 128);
    conv3x3_kernel<true><<<g128, 256>>>(f2, w3T, b3, f1, 128, 128);

    dim3 ghead(4, 16, 4 * 1);
    conv3x3_kernel<false><<<ghead, 256>>>(f1, w4T, b4p, headp, 128, 32);

    dim3 gdef(8, 32, 4);       // Wtiles(16), Htiles(4), B
    deform_kernel<<<gdef, 256>>>(x, headp, flow, wdT, bd, out);
}